// round 9
// baseline (speedup 1.0000x reference)
#include <cuda_runtime.h>
#include <cuda_bf16.h>
#include <mma.h>
#include <math.h>
#include <stdint.h>

using namespace nvcuda;

// ---------------------------------------------------------------------------
// RGCN layer (plain sm_103 target: WMMA bf16 + cp.async, no tcgen05).
//   S[d]  = sum_{e: dst=d} (h[src] + emb_rel[etype])         (edge pass)
//   main  = (norm.S) @ Wn + h @ Wl     (phases 0-1, K-concat into acc_main)
//   skip  = prev @ Wsk                 (phase 2, acc_gate; prev stays in SMEM)
//   out   = relu(g*main + (1-g)*prev),  g = sigmoid(skip + b)
//   deg-0 nodes (~250): recompute loop term with W_evolve in fix_kernel.
// Split precision: x = hi(bf16)+lo(bf16); hi*hi + hi*lo + lo*hi, fp32 acc
// (err ~2^-16). k-outer/product-inner loop shares fragments (8 LDSM per
// k-step for 12 MMAs); cp.async pipelines the next A tile behind the gemm.
// ---------------------------------------------------------------------------

#define D    128
#define NMAX 100000
#define LDA  136
#define LDB  136

__device__ float4 g_S4[NMAX * (D / 4)];     // 51.2 MB scatter accumulator
__device__ int    g_flag[NMAX];
__device__ int    g_list[NMAX];
__device__ int    g_cnt;
__device__ __nv_bfloat16 g_WtH[3][D * D];   // W^T hi (Wn, Wl, Wsk), [n*D+k]
__device__ __nv_bfloat16 g_WtL[3][D * D];   // W^T lo

// ---------------------------------------------------------------------------
__device__ __forceinline__ uint32_t smem_u32(const void* p) {
    uint32_t a;
    asm("{ .reg .u64 t; cvta.to.shared.u64 t, %1; cvt.u32.u64 %0, t; }"
        : "=r"(a) : "l"(p));
    return a;
}
__device__ __forceinline__ void cp16(uint32_t saddr, const void* g) {
    asm volatile("cp.async.cg.shared.global [%0], [%1], 16;"
                 :: "r"(saddr), "l"(g));
}
#define CP_COMMIT() asm volatile("cp.async.commit_group;" ::: "memory")
#define CP_WAIT0()  asm volatile("cp.async.wait_group 0;" ::: "memory")

// ---------------------------------------------------------------------------
// Edge pass: one warp per edge, lane l handles floats [4l,4l+4).
// ---------------------------------------------------------------------------
__global__ void edge_kernel(const float* __restrict__ h,
                            const float* __restrict__ emb,
                            const int* __restrict__ src,
                            const int* __restrict__ dst,
                            const int* __restrict__ et, int E) {
    int w = (blockIdx.x * blockDim.x + threadIdx.x) >> 5;
    if (w >= E) return;
    int lane = threadIdx.x & 31;
    int s = __ldg(src + w);
    int d = __ldg(dst + w);
    int r = __ldg(et + w);
    float4 hv = ((const float4*)(h + (size_t)s * D))[lane];
    float4 rv = ((const float4*)(emb + (size_t)r * D))[lane];
    float4 v = make_float4(hv.x + rv.x, hv.y + rv.y, hv.z + rv.z, hv.w + rv.w);
    float* p = (float*)&g_S4[(size_t)d * (D / 4) + lane];
    asm volatile("red.global.add.v4.f32 [%0], {%1,%2,%3,%4};"
                 :: "l"(p), "f"(v.x), "f"(v.y), "f"(v.z), "f"(v.w) : "memory");
    if (lane == 0) g_flag[d] = 1;
}

__global__ void build_list(int N) {
    int n = blockIdx.x * blockDim.x + threadIdx.x;
    if (n < N && g_flag[n] == 0) {
        int p = atomicAdd(&g_cnt, 1);
        g_list[p] = n;
    }
}

// ---------------------------------------------------------------------------
// Weight transpose + bf16 hi/lo split:  Wt[n,k] = W[k,n]
// ---------------------------------------------------------------------------
__global__ void wtrans(const float* __restrict__ Wn,
                       const float* __restrict__ Wl,
                       const float* __restrict__ Wsk) {
    int id = blockIdx.x * 256 + threadIdx.x;          // 0..49151
    if (id >= 3 * D * D) return;
    int k = id & 127, n = (id >> 7) & 127, w = id >> 14;
    const float* W = (w == 0) ? Wn : (w == 1) ? Wl : Wsk;
    float x = W[k * D + n];
    __nv_bfloat16 hi = __float2bfloat16(x);
    float r = x - __bfloat162float(hi);
    g_WtH[w][n * D + k] = hi;
    g_WtL[w][n * D + k] = __float2bfloat16(r);
}

// ---------------------------------------------------------------------------
// Node pass: per block M=128 nodes x N=128 outputs, 512 threads = 16 warps
// tiled 4(M) x 4(N); warp tile 32x32 = 2x2 fp32 acc frags (main + gate).
// SMEM: A hi/lo + B hi/lo (4x34816) + RAW fp32 (65536) = 204800 B.
// ---------------------------------------------------------------------------
#define OFF_AHI 0
#define OFF_ALO 34816
#define OFF_BHI 69632
#define OFF_BLO 104448
#define OFF_RAW 139264
#define SM_TOT  204800

typedef wmma::fragment<wmma::matrix_a, 16, 16, 16, __nv_bfloat16, wmma::row_major> FragA;
typedef wmma::fragment<wmma::matrix_b, 16, 16, 16, __nv_bfloat16, wmma::col_major> FragB;
typedef wmma::fragment<wmma::accumulator, 16, 16, 16, float> FragC;

// async copy of a 128x128 fp32 tile into RAW (rows >= N skipped)
__device__ __forceinline__ void cpasync_raw(uint32_t sbase,
                                            const float* __restrict__ X,
                                            int node0, int N, int tid) {
    #pragma unroll 2
    for (int i = tid; i < 4096; i += 512) {
        int row = i >> 5, gr = node0 + row;
        if (gr < N)
            cp16(sbase + OFF_RAW + i * 16, X + (size_t)gr * D + (i & 31) * 4);
    }
    CP_COMMIT();
}

// RAW fp32 -> A hi/lo bf16 split tiles (optionally scaled by rowscale)
__device__ __forceinline__ void convert_A(char* sm,
                                          const float* __restrict__ rowscale,
                                          int node0, int N, int tid) {
    const float4* raw = (const float4*)(sm + OFF_RAW);
    __nv_bfloat16* sHi = (__nv_bfloat16*)(sm + OFF_AHI);
    __nv_bfloat16* sLo = (__nv_bfloat16*)(sm + OFF_ALO);
    #pragma unroll 2
    for (int i = tid; i < 4096; i += 512) {
        int row = i >> 5, c4 = i & 31, gr = node0 + row;
        float4 v = make_float4(0.f, 0.f, 0.f, 0.f);
        float sc = 1.f;
        if (gr < N) {
            v = raw[i];
            if (rowscale) sc = __ldg(rowscale + gr);
        }
        float x0 = v.x * sc, x1 = v.y * sc, x2 = v.z * sc, x3 = v.w * sc;
        __nv_bfloat16 h0 = __float2bfloat16(x0), h1 = __float2bfloat16(x1);
        __nv_bfloat16 h2 = __float2bfloat16(x2), h3 = __float2bfloat16(x3);
        __nv_bfloat162 H01; H01.x = h0; H01.y = h1;
        __nv_bfloat162 H23; H23.x = h2; H23.y = h3;
        __nv_bfloat162 L01, L23;
        L01.x = __float2bfloat16(x0 - __bfloat162float(h0));
        L01.y = __float2bfloat16(x1 - __bfloat162float(h1));
        L23.x = __float2bfloat16(x2 - __bfloat162float(h2));
        L23.y = __float2bfloat16(x3 - __bfloat162float(h3));
        int off = row * LDA + c4 * 4;
        *(__nv_bfloat162*)(sHi + off)     = H01;
        *(__nv_bfloat162*)(sHi + off + 2) = H23;
        *(__nv_bfloat162*)(sLo + off)     = L01;
        *(__nv_bfloat162*)(sLo + off + 2) = L23;
    }
}

// async copy W^T hi/lo into B tiles
__device__ __forceinline__ void cpasync_B(uint32_t sbase,
                                          const __nv_bfloat16* __restrict__ WH,
                                          const __nv_bfloat16* __restrict__ WL,
                                          int tid) {
    #pragma unroll 2
    for (int i = tid; i < 2048; i += 512) {   // 16 B = 8 bf16
        int n = i >> 4, kq = i & 15;
        uint32_t soff = (uint32_t)(n * LDB + kq * 8) * 2;
        cp16(sbase + OFF_BHI + soff, WH + n * D + kq * 8);
        cp16(sbase + OFF_BLO + soff, WL + n * D + kq * 8);
    }
    CP_COMMIT();
}

// k-outer, product-inner: 8 fragment loads per k-step feed 12 MMAs
__device__ __forceinline__ void gemm3(char* sm, FragC acc[2][2],
                                      int warp_m, int warp_n) {
    const __nv_bfloat16* sAHi = (const __nv_bfloat16*)(sm + OFF_AHI);
    const __nv_bfloat16* sALo = (const __nv_bfloat16*)(sm + OFF_ALO);
    const __nv_bfloat16* sBHi = (const __nv_bfloat16*)(sm + OFF_BHI);
    const __nv_bfloat16* sBLo = (const __nv_bfloat16*)(sm + OFF_BLO);
    #pragma unroll 1
    for (int k = 0; k < 8; k++) {
        FragA ah[2], al[2];
        FragB bh[2], bl[2];
        #pragma unroll
        for (int i = 0; i < 2; i++) {
            wmma::load_matrix_sync(ah[i],
                sAHi + (warp_m * 32 + i * 16) * LDA + k * 16, LDA);
            wmma::load_matrix_sync(al[i],
                sALo + (warp_m * 32 + i * 16) * LDA + k * 16, LDA);
        }
        #pragma unroll
        for (int j = 0; j < 2; j++) {
            wmma::load_matrix_sync(bh[j],
                sBHi + (warp_n * 32 + j * 16) * LDB + k * 16, LDB);
            wmma::load_matrix_sync(bl[j],
                sBLo + (warp_n * 32 + j * 16) * LDB + k * 16, LDB);
        }
        #pragma unroll
        for (int i = 0; i < 2; i++)
            #pragma unroll
            for (int j = 0; j < 2; j++) {
                wmma::mma_sync(acc[i][j], ah[i], bh[j], acc[i][j]);
                wmma::mma_sync(acc[i][j], ah[i], bl[j], acc[i][j]);
                wmma::mma_sync(acc[i][j], al[i], bh[j], acc[i][j]);
            }
    }
}

__global__ void __launch_bounds__(512)
node_wmma(const float* __restrict__ h, const float* __restrict__ prev,
          const float* __restrict__ norm, const float* __restrict__ bias,
          float* __restrict__ out, int N) {
    extern __shared__ char sm[];
    uint32_t sbase = smem_u32(sm);
    int tid = threadIdx.x;
    int wid = tid >> 5;
    int warp_m = wid & 3, warp_n = wid >> 2;
    int node0 = blockIdx.x * 128;
    FragC acc_main[2][2], acc_gate[2][2];
    #pragma unroll
    for (int i = 0; i < 2; i++)
        #pragma unroll
        for (int j = 0; j < 2; j++) {
            wmma::fill_fragment(acc_main[i][j], 0.f);
            wmma::fill_fragment(acc_gate[i][j], 0.f);
        }

    const float* Xs[3] = {(const float*)g_S4, h, prev};
    cpasync_raw(sbase, Xs[0], node0, N, tid);     // prefetch S

    #pragma unroll 1
    for (int ph = 0; ph < 3; ph++) {
        CP_WAIT0();                               // RAW(ph) landed
        __syncthreads();                          // prev gemm done reading A/B
        cpasync_B(sbase, g_WtH[ph], g_WtL[ph], tid);
        convert_A(sm, ph == 0 ? norm : nullptr, node0, N, tid);
        CP_WAIT0();                               // B landed
        __syncthreads();                          // tiles visible to all
        if (ph < 2) cpasync_raw(sbase, Xs[ph + 1], node0, N, tid);
        gemm3(sm, ph < 2 ? acc_main : acc_gate, warp_m, warp_n);
    }
    __syncthreads();                              // gemm done; B/RAW reusable

    // ---- epilogue: sMain (B region, ld=136) + sGate (RAW, ld=128) ----
    float* sMain = (float*)(sm + OFF_BHI);        // 128*136*4 = 69632 B
    float* sGate = (float*)(sm + OFF_RAW);        // 128*128*4 = 65536 B
    #pragma unroll
    for (int i = 0; i < 2; i++)
        #pragma unroll
        for (int j = 0; j < 2; j++) {
            wmma::store_matrix_sync(
                sMain + (warp_m * 32 + i * 16) * 136 + warp_n * 32 + j * 16,
                acc_main[i][j], 136, wmma::mem_row_major);
            wmma::store_matrix_sync(
                sGate + (warp_m * 32 + i * 16) * 128 + warp_n * 32 + j * 16,
                acc_gate[i][j], 128, wmma::mem_row_major);
        }
    __syncthreads();

    const __nv_bfloat16* sHi = (const __nv_bfloat16*)(sm + OFF_AHI); // prev hi
    const __nv_bfloat16* sLo = (const __nv_bfloat16*)(sm + OFF_ALO); // prev lo
    #pragma unroll 2
    for (int i = tid; i < 4096; i += 512) {
        int m = i >> 5, c4 = i & 31;
        if (node0 + m >= N) continue;
        float4 mn = *(const float4*)(sMain + m * 136 + c4 * 4);
        float4 z  = ((const float4*)sGate)[m * 32 + c4];
        float4 bz = ((const float4*)bias)[c4];
        int off = m * LDA + c4 * 4;
        __nv_bfloat162 H01 = *(const __nv_bfloat162*)(sHi + off);
        __nv_bfloat162 H23 = *(const __nv_bfloat162*)(sHi + off + 2);
        __nv_bfloat162 L01 = *(const __nv_bfloat162*)(sLo + off);
        __nv_bfloat162 L23 = *(const __nv_bfloat162*)(sLo + off + 2);
        float p0 = __bfloat162float(H01.x) + __bfloat162float(L01.x);
        float p1 = __bfloat162float(H01.y) + __bfloat162float(L01.y);
        float p2 = __bfloat162float(H23.x) + __bfloat162float(L23.x);
        float p3 = __bfloat162float(H23.y) + __bfloat162float(L23.y);
        float4 o;
        float g;
        g = 1.f / (1.f + __expf(-(z.x + bz.x)));
        o.x = fmaxf(g * mn.x + (1.f - g) * p0, 0.f);
        g = 1.f / (1.f + __expf(-(z.y + bz.y)));
        o.y = fmaxf(g * mn.y + (1.f - g) * p1, 0.f);
        g = 1.f / (1.f + __expf(-(z.z + bz.z)));
        o.z = fmaxf(g * mn.z + (1.f - g) * p2, 0.f);
        g = 1.f / (1.f + __expf(-(z.w + bz.w)));
        o.w = fmaxf(g * mn.w + (1.f - g) * p3, 0.f);
        ((float4*)(out + (size_t)(node0 + m) * D))[c4] = o;
    }
}

// ---------------------------------------------------------------------------
// Fix-up for degree-0 nodes (agg==0): out = relu(g*(h@We) + (1-g)*prev)
// ---------------------------------------------------------------------------
__global__ void fix_kernel(const float* __restrict__ h,
                           const float* __restrict__ prev,
                           const float* __restrict__ We,
                           const float* __restrict__ Wsk,
                           const float* __restrict__ bias,
                           float* __restrict__ out) {
    __shared__ float sh[D], sp[D];
    int t = threadIdx.x;
    int cnt = g_cnt;
    for (int ii = blockIdx.x; ii < cnt; ii += gridDim.x) {
        int node = g_list[ii];
        __syncthreads();
        sh[t] = h[(size_t)node * D + t];
        sp[t] = prev[(size_t)node * D + t];
        __syncthreads();
        float lp = 0.f, sk = 0.f;
        #pragma unroll 8
        for (int k = 0; k < D; k++) {
            lp = fmaf(sh[k], __ldg(We  + k * D + t), lp);
            sk = fmaf(sp[k], __ldg(Wsk + k * D + t), sk);
        }
        float g = 1.f / (1.f + __expf(-(sk + bias[t])));
        out[(size_t)node * D + t] = fmaxf(g * lp + (1.f - g) * sp[t], 0.f);
    }
}

// ---------------------------------------------------------------------------
extern "C" void kernel_launch(void* const* d_in, const int* in_sizes, int n_in,
                              void* d_out, int out_size) {
    const float* h    = (const float*)d_in[0];
    const float* prev = (const float*)d_in[1];
    const float* emb  = (const float*)d_in[2];
    const float* norm = (const float*)d_in[3];
    const float* Wn   = (const float*)d_in[4];
    const float* Wl   = (const float*)d_in[5];
    const float* We   = (const float*)d_in[6];
    const float* Wsk  = (const float*)d_in[7];
    const float* bias = (const float*)d_in[8];
    const int* src = (const int*)d_in[9];     // int32 (JAX x64-disabled)
    const int* dst = (const int*)d_in[10];
    const int* et  = (const int*)d_in[11];
    int N = in_sizes[3];
    if (N > NMAX) N = NMAX;
    int E = in_sizes[9];
    float* out = (float*)d_out;

    void *pS, *pF, *pC;
    cudaGetSymbolAddress(&pS, g_S4);
    cudaGetSymbolAddress(&pF, g_flag);
    cudaGetSymbolAddress(&pC, g_cnt);
    cudaMemsetAsync(pS, 0, (size_t)N * D * sizeof(float), 0);
    cudaMemsetAsync(pF, 0, (size_t)N * sizeof(int), 0);
    cudaMemsetAsync(pC, 0, sizeof(int), 0);

    wtrans<<<192, 256>>>(Wn, Wl, Wsk);

    int edgeBlocks = (E + 7) / 8;
    edge_kernel<<<edgeBlocks, 256>>>(h, emb, src, dst, et, E);

    build_list<<<(N + 255) / 256, 256>>>(N);

    cudaFuncSetAttribute(node_wmma,
                         cudaFuncAttributeMaxDynamicSharedMemorySize, SM_TOT);
    node_wmma<<<(N + 127) / 128, 512, SM_TOT>>>(h, prev, norm, bias, out, N);

    fix_kernel<<<2048, 128>>>(h, prev, We, Wsk, bias, out);
}

// round 14
// speedup vs baseline: 1.4595x; 1.4595x over previous
#include <cuda_runtime.h>
#include <cuda_bf16.h>
#include <mma.h>
#include <math.h>
#include <stdint.h>

using namespace nvcuda;

// ---------------------------------------------------------------------------
// RGCN layer (plain sm_103 target: WMMA bf16, no tcgen05).
//   S[d]  = sum_{e: dst=d} (h[src] + emb_rel[etype])         (edge pass)
//   main  = (norm.S) @ Wn + h @ Wl     (phases 0-1, one acc set, K-concat)
//   park main in SMEM; gate = prev @ Wsk (phase 2, SAME acc set re-filled)
//   out   = relu(g*main + (1-g)*prev),  g = sigmoid(gate + b)
//   deg-0 nodes (~250): recompute loop term with W_evolve in fix_kernel.
// Split precision: x = hi(bf16)+lo(bf16); hi*hi + hi*lo + lo*hi, fp32 acc
// (err ~2^-16). k-outer/product-inner: 8 LDSM per k-step feed 12 MMAs.
// ONE accumulator set live at any time (R9's two live sets spilled: regs
// clamped to 64, L2 45% from local-memory traffic, node 222->336us).
// ---------------------------------------------------------------------------

#define D    128
#define NMAX 100000
#define LDA  136
#define LDB  136

__device__ float4 g_S4[NMAX * (D / 4)];     // 51.2 MB scatter accumulator
__device__ int    g_flag[NMAX];
__device__ int    g_list[NMAX];
__device__ int    g_cnt;
__device__ __nv_bfloat16 g_WtH[3][D * D];   // W^T hi (Wn, Wl, Wsk), [n*D+k]
__device__ __nv_bfloat16 g_WtL[3][D * D];   // W^T lo

// ---------------------------------------------------------------------------
// Edge pass: one warp per edge, lane l handles floats [4l,4l+4).
// ---------------------------------------------------------------------------
__global__ void edge_kernel(const float* __restrict__ h,
                            const float* __restrict__ emb,
                            const int* __restrict__ src,
                            const int* __restrict__ dst,
                            const int* __restrict__ et, int E) {
    int w = (blockIdx.x * blockDim.x + threadIdx.x) >> 5;
    if (w >= E) return;
    int lane = threadIdx.x & 31;
    int s = __ldg(src + w);
    int d = __ldg(dst + w);
    int r = __ldg(et + w);
    float4 hv = ((const float4*)(h + (size_t)s * D))[lane];
    float4 rv = ((const float4*)(emb + (size_t)r * D))[lane];
    float4 v = make_float4(hv.x + rv.x, hv.y + rv.y, hv.z + rv.z, hv.w + rv.w);
    float* p = (float*)&g_S4[(size_t)d * (D / 4) + lane];
    asm volatile("red.global.add.v4.f32 [%0], {%1,%2,%3,%4};"
                 :: "l"(p), "f"(v.x), "f"(v.y), "f"(v.z), "f"(v.w) : "memory");
    if (lane == 0) g_flag[d] = 1;
}

__global__ void build_list(int N) {
    int n = blockIdx.x * blockDim.x + threadIdx.x;
    if (n < N && g_flag[n] == 0) {
        int p = atomicAdd(&g_cnt, 1);
        g_list[p] = n;
    }
}

// ---------------------------------------------------------------------------
// Weight transpose + bf16 hi/lo split:  Wt[n,k] = W[k,n]
// ---------------------------------------------------------------------------
__global__ void wtrans(const float* __restrict__ Wn,
                       const float* __restrict__ Wl,
                       const float* __restrict__ Wsk) {
    int id = blockIdx.x * 256 + threadIdx.x;          // 0..49151
    if (id >= 3 * D * D) return;
    int k = id & 127, n = (id >> 7) & 127, w = id >> 14;
    const float* W = (w == 0) ? Wn : (w == 1) ? Wl : Wsk;
    float x = W[k * D + n];
    __nv_bfloat16 hi = __float2bfloat16(x);
    float r = x - __bfloat162float(hi);
    g_WtH[w][n * D + k] = hi;
    g_WtL[w][n * D + k] = __float2bfloat16(r);
}

// ---------------------------------------------------------------------------
// Node pass: per block M=128 nodes x N=128 outputs, 512 threads = 16 warps
// tiled 4(M) x 4(N); warp tile 32x32 = 2x2 fp32 acc frags (single set).
// SMEM: A hi/lo + B hi/lo (4x34816) + MAIN fp32 (65536) = 204800 B.
// ---------------------------------------------------------------------------
#define OFF_AHI  0
#define OFF_ALO  34816
#define OFF_BHI  69632
#define OFF_BLO  104448
#define OFF_MAIN 139264
#define SM_TOT   204800

typedef wmma::fragment<wmma::matrix_a, 16, 16, 16, __nv_bfloat16, wmma::row_major> FragA;
typedef wmma::fragment<wmma::matrix_b, 16, 16, 16, __nv_bfloat16, wmma::col_major> FragB;
typedef wmma::fragment<wmma::accumulator, 16, 16, 16, float> FragC;

__device__ __forceinline__ void stage_X(char* sm, const float* __restrict__ X,
                                        const float* __restrict__ rowscale,
                                        int node0, int N, int tid) {
    __nv_bfloat16* sHi = (__nv_bfloat16*)(sm + OFF_AHI);
    __nv_bfloat16* sLo = (__nv_bfloat16*)(sm + OFF_ALO);
    #pragma unroll 2
    for (int i = tid; i < 128 * 32; i += 512) {
        int row = i >> 5, c4 = i & 31;
        float4 v = make_float4(0.f, 0.f, 0.f, 0.f);
        int gr = node0 + row;
        float sc = 1.f;
        if (gr < N) {
            v = ((const float4*)(X + (size_t)gr * D))[c4];
            if (rowscale) sc = __ldg(rowscale + gr);
        }
        float x0 = v.x * sc, x1 = v.y * sc, x2 = v.z * sc, x3 = v.w * sc;
        __nv_bfloat16 h0 = __float2bfloat16(x0), h1 = __float2bfloat16(x1);
        __nv_bfloat16 h2 = __float2bfloat16(x2), h3 = __float2bfloat16(x3);
        __nv_bfloat162 H01; H01.x = h0; H01.y = h1;
        __nv_bfloat162 H23; H23.x = h2; H23.y = h3;
        __nv_bfloat162 L01, L23;
        L01.x = __float2bfloat16(x0 - __bfloat162float(h0));
        L01.y = __float2bfloat16(x1 - __bfloat162float(h1));
        L23.x = __float2bfloat16(x2 - __bfloat162float(h2));
        L23.y = __float2bfloat16(x3 - __bfloat162float(h3));
        int off = row * LDA + c4 * 4;
        *(__nv_bfloat162*)(sHi + off)     = H01;
        *(__nv_bfloat162*)(sHi + off + 2) = H23;
        *(__nv_bfloat162*)(sLo + off)     = L01;
        *(__nv_bfloat162*)(sLo + off + 2) = L23;
    }
}

__device__ __forceinline__ void stage_B(char* sm,
                                        const __nv_bfloat16* __restrict__ WH,
                                        const __nv_bfloat16* __restrict__ WL,
                                        int tid) {
    __nv_bfloat16* sBH = (__nv_bfloat16*)(sm + OFF_BHI);
    __nv_bfloat16* sBL = (__nv_bfloat16*)(sm + OFF_BLO);
    #pragma unroll 2
    for (int i = tid; i < 128 * 16; i += 512) {   // uint4 = 8 bf16
        int n = i >> 4, kq = i & 15;
        *(uint4*)(sBH + n * LDB + kq * 8) = *(const uint4*)(WH + n * D + kq * 8);
        *(uint4*)(sBL + n * LDB + kq * 8) = *(const uint4*)(WL + n * D + kq * 8);
    }
}

// k-outer, product-inner: 8 fragment loads per k-step feed 12 MMAs
__device__ __forceinline__ void gemm3(char* sm, FragC acc[2][2],
                                      int warp_m, int warp_n) {
    const __nv_bfloat16* sAHi = (const __nv_bfloat16*)(sm + OFF_AHI);
    const __nv_bfloat16* sALo = (const __nv_bfloat16*)(sm + OFF_ALO);
    const __nv_bfloat16* sBHi = (const __nv_bfloat16*)(sm + OFF_BHI);
    const __nv_bfloat16* sBLo = (const __nv_bfloat16*)(sm + OFF_BLO);
    #pragma unroll 1
    for (int k = 0; k < 8; k++) {
        FragA ah[2], al[2];
        FragB bh[2], bl[2];
        #pragma unroll
        for (int i = 0; i < 2; i++) {
            wmma::load_matrix_sync(ah[i],
                sAHi + (warp_m * 32 + i * 16) * LDA + k * 16, LDA);
            wmma::load_matrix_sync(al[i],
                sALo + (warp_m * 32 + i * 16) * LDA + k * 16, LDA);
        }
        #pragma unroll
        for (int j = 0; j < 2; j++) {
            wmma::load_matrix_sync(bh[j],
                sBHi + (warp_n * 32 + j * 16) * LDB + k * 16, LDB);
            wmma::load_matrix_sync(bl[j],
                sBLo + (warp_n * 32 + j * 16) * LDB + k * 16, LDB);
        }
        #pragma unroll
        for (int i = 0; i < 2; i++)
            #pragma unroll
            for (int j = 0; j < 2; j++) {
                wmma::mma_sync(acc[i][j], ah[i], bh[j], acc[i][j]);
                wmma::mma_sync(acc[i][j], ah[i], bl[j], acc[i][j]);
                wmma::mma_sync(acc[i][j], al[i], bh[j], acc[i][j]);
            }
    }
}

__global__ void __launch_bounds__(512)
node_wmma(const float* __restrict__ h, const float* __restrict__ prev,
          const float* __restrict__ norm, const float* __restrict__ bias,
          float* __restrict__ out, int N) {
    extern __shared__ char sm[];
    float* sMain = (float*)(sm + OFF_MAIN);   // 128x128 f32 (ld=128)
    float* sGate = (float*)(sm + OFF_BHI);    // aliases B region post-gemm
    int tid = threadIdx.x;
    int wid = tid >> 5;
    int warp_m = wid & 3, warp_n = wid >> 2;
    int node0 = blockIdx.x * 128;
    FragC acc[2][2];

    // ---- Phases 0+1: main = (norm.S) @ Wn + h @ Wl (K-concat, one acc) ----
    #pragma unroll
    for (int i = 0; i < 2; i++)
        #pragma unroll
        for (int j = 0; j < 2; j++) wmma::fill_fragment(acc[i][j], 0.f);
    stage_X(sm, (const float*)g_S4, norm, node0, N, tid);
    stage_B(sm, g_WtH[0], g_WtL[0], tid);
    __syncthreads();
    gemm3(sm, acc, warp_m, warp_n);
    __syncthreads();                          // gemm reads done, restage
    stage_X(sm, h, nullptr, node0, N, tid);
    stage_B(sm, g_WtH[1], g_WtL[1], tid);
    __syncthreads();
    gemm3(sm, acc, warp_m, warp_n);
    // park main in SMEM (separate region; A/B untouched by these stores)
    #pragma unroll
    for (int i = 0; i < 2; i++)
        #pragma unroll
        for (int j = 0; j < 2; j++)
            wmma::store_matrix_sync(
                sMain + (warp_m * 32 + i * 16) * 128 + warp_n * 32 + j * 16,
                acc[i][j], 128, wmma::mem_row_major);
    __syncthreads();                          // gemm + park done, restage

    // ---- Phase 2: gate = prev @ Wsk (same acc set re-filled) ----
    #pragma unroll
    for (int i = 0; i < 2; i++)
        #pragma unroll
        for (int j = 0; j < 2; j++) wmma::fill_fragment(acc[i][j], 0.f);
    stage_X(sm, prev, nullptr, node0, N, tid);
    stage_B(sm, g_WtH[2], g_WtL[2], tid);
    __syncthreads();
    gemm3(sm, acc, warp_m, warp_n);
    __syncthreads();                          // B reads done; alias as sGate
    #pragma unroll
    for (int i = 0; i < 2; i++)
        #pragma unroll
        for (int j = 0; j < 2; j++)
            wmma::store_matrix_sync(
                sGate + (warp_m * 32 + i * 16) * 128 + warp_n * 32 + j * 16,
                acc[i][j], 128, wmma::mem_row_major);
    __syncthreads();

    // ---- Epilogue: out = relu(g*main + (1-g)*prev); prev from A tiles ----
    const __nv_bfloat16* sHi = (const __nv_bfloat16*)(sm + OFF_AHI);
    const __nv_bfloat16* sLo = (const __nv_bfloat16*)(sm + OFF_ALO);
    #pragma unroll 2
    for (int i = tid; i < 4096; i += 512) {
        int m = i >> 5, c4 = i & 31;
        if (node0 + m >= N) continue;
        float4 mn = ((const float4*)sMain)[m * 32 + c4];
        float4 z  = ((const float4*)sGate)[m * 32 + c4];
        float4 bz = ((const float4*)bias)[c4];
        int off = m * LDA + c4 * 4;
        __nv_bfloat162 H01 = *(const __nv_bfloat162*)(sHi + off);
        __nv_bfloat162 H23 = *(const __nv_bfloat162*)(sHi + off + 2);
        __nv_bfloat162 L01 = *(const __nv_bfloat162*)(sLo + off);
        __nv_bfloat162 L23 = *(const __nv_bfloat162*)(sLo + off + 2);
        float p0 = __bfloat162float(H01.x) + __bfloat162float(L01.x);
        float p1 = __bfloat162float(H01.y) + __bfloat162float(L01.y);
        float p2 = __bfloat162float(H23.x) + __bfloat162float(L23.x);
        float p3 = __bfloat162float(H23.y) + __bfloat162float(L23.y);
        float4 o;
        float g;
        g = 1.f / (1.f + __expf(-(z.x + bz.x)));
        o.x = fmaxf(g * mn.x + (1.f - g) * p0, 0.f);
        g = 1.f / (1.f + __expf(-(z.y + bz.y)));
        o.y = fmaxf(g * mn.y + (1.f - g) * p1, 0.f);
        g = 1.f / (1.f + __expf(-(z.z + bz.z)));
        o.z = fmaxf(g * mn.z + (1.f - g) * p2, 0.f);
        g = 1.f / (1.f + __expf(-(z.w + bz.w)));
        o.w = fmaxf(g * mn.w + (1.f - g) * p3, 0.f);
        ((float4*)(out + (size_t)(node0 + m) * D))[c4] = o;
    }
}

// ---------------------------------------------------------------------------
// Fix-up for degree-0 nodes (agg==0): out = relu(g*(h@We) + (1-g)*prev)
// ---------------------------------------------------------------------------
__global__ void fix_kernel(const float* __restrict__ h,
                           const float* __restrict__ prev,
                           const float* __restrict__ We,
                           const float* __restrict__ Wsk,
                           const float* __restrict__ bias,
                           float* __restrict__ out) {
    __shared__ float sh[D], sp[D];
    int t = threadIdx.x;
    int cnt = g_cnt;
    for (int ii = blockIdx.x; ii < cnt; ii += gridDim.x) {
        int node = g_list[ii];
        __syncthreads();
        sh[t] = h[(size_t)node * D + t];
        sp[t] = prev[(size_t)node * D + t];
        __syncthreads();
        float lp = 0.f, sk = 0.f;
        #pragma unroll 8
        for (int k = 0; k < D; k++) {
            lp = fmaf(sh[k], __ldg(We  + k * D + t), lp);
            sk = fmaf(sp[k], __ldg(Wsk + k * D + t), sk);
        }
        float g = 1.f / (1.f + __expf(-(sk + bias[t])));
        out[(size_t)node * D + t] = fmaxf(g * lp + (1.f - g) * sp[t], 0.f);
    }
}

// ---------------------------------------------------------------------------
extern "C" void kernel_launch(void* const* d_in, const int* in_sizes, int n_in,
                              void* d_out, int out_size) {
    const float* h    = (const float*)d_in[0];
    const float* prev = (const float*)d_in[1];
    const float* emb  = (const float*)d_in[2];
    const float* norm = (const float*)d_in[3];
    const float* Wn   = (const float*)d_in[4];
    const float* Wl   = (const float*)d_in[5];
    const float* We   = (const float*)d_in[6];
    const float* Wsk  = (const float*)d_in[7];
    const float* bias = (const float*)d_in[8];
    const int* src = (const int*)d_in[9];     // int32 (JAX x64-disabled)
    const int* dst = (const int*)d_in[10];
    const int* et  = (const int*)d_in[11];
    int N = in_sizes[3];
    if (N > NMAX) N = NMAX;
    int E = in_sizes[9];
    float* out = (float*)d_out;

    void *pS, *pF, *pC;
    cudaGetSymbolAddress(&pS, g_S4);
    cudaGetSymbolAddress(&pF, g_flag);
    cudaGetSymbolAddress(&pC, g_cnt);
    cudaMemsetAsync(pS, 0, (size_t)N * D * sizeof(float), 0);
    cudaMemsetAsync(pF, 0, (size_t)N * sizeof(int), 0);
    cudaMemsetAsync(pC, 0, sizeof(int), 0);

    wtrans<<<192, 256>>>(Wn, Wl, Wsk);

    int edgeBlocks = (E + 7) / 8;
    edge_kernel<<<edgeBlocks, 256>>>(h, emb, src, dst, et, E);

    build_list<<<(N + 255) / 256, 256>>>(N);

    cudaFuncSetAttribute(node_wmma,
                         cudaFuncAttributeMaxDynamicSharedMemorySize, SM_TOT);
    node_wmma<<<(N + 127) / 128, 512, SM_TOT>>>(h, prev, norm, bias, out, N);

    fix_kernel<<<2048, 128>>>(h, prev, We, Wsk, bias, out);
}

// round 16
// speedup vs baseline: 1.5625x; 1.0705x over previous
#include <cuda_runtime.h>
#include <cuda_bf16.h>
#include <mma.h>
#include <math.h>
#include <stdint.h>

using namespace nvcuda;

// ---------------------------------------------------------------------------
// RGCN layer (plain sm_103 target: WMMA bf16 + cp.async, no tcgen05).
//   S[d]  = sum_{e: dst=d} (h[src] + emb_rel[etype])         (edge pass)
//   main  = (norm.S) @ Wn + h @ Wl     (phases 0-1, ONE acc set, K-concat)
//   gate  = prev @ Wsk                 (phase 2, same acc refilled)
//   out   = relu(g*main + (1-g)*prev),  g = sigmoid(gate + b)
//   deg-0 nodes (~250): recompute loop term with W_evolve in fix_kernel.
// Split precision: x = hi(bf16)+lo(bf16); hi*hi + hi*lo + lo*hi, fp32 acc.
// cp.async pipelines the NEXT phase's fp32 X tile into RAW during the gemm;
// RAW doubles as the MAIN parking buffer once prev is converted out (this is
// what makes the pipeline fit in 204800 B where R9's version could not, and
// the single live acc set avoids R9's register spill).
// ---------------------------------------------------------------------------

#define D    128
#define NMAX 100000
#define LDA  136
#define LDB  136

__device__ float4 g_S4[NMAX * (D / 4)];     // 51.2 MB scatter accumulator
__device__ int    g_flag[NMAX];
__device__ int    g_list[NMAX];
__device__ int    g_cnt;
__device__ __nv_bfloat16 g_WtH[3][D * D];   // W^T hi (Wn, Wl, Wsk), [n*D+k]
__device__ __nv_bfloat16 g_WtL[3][D * D];   // W^T lo

// ---------------------------------------------------------------------------
__device__ __forceinline__ uint32_t smem_u32(const void* p) {
    uint32_t a;
    asm("{ .reg .u64 t; cvta.to.shared.u64 t, %1; cvt.u32.u64 %0, t; }"
        : "=r"(a) : "l"(p));
    return a;
}
__device__ __forceinline__ void cp16(uint32_t saddr, const void* g) {
    asm volatile("cp.async.cg.shared.global [%0], [%1], 16;"
                 :: "r"(saddr), "l"(g));
}
#define CP_COMMIT() asm volatile("cp.async.commit_group;" ::: "memory")
#define CP_WAIT0()  asm volatile("cp.async.wait_group 0;" ::: "memory")

// ---------------------------------------------------------------------------
// Edge pass: one warp per edge, lane l handles floats [4l,4l+4).
// ---------------------------------------------------------------------------
__global__ void edge_kernel(const float* __restrict__ h,
                            const float* __restrict__ emb,
                            const int* __restrict__ src,
                            const int* __restrict__ dst,
                            const int* __restrict__ et, int E) {
    int w = (blockIdx.x * blockDim.x + threadIdx.x) >> 5;
    if (w >= E) return;
    int lane = threadIdx.x & 31;
    int s = __ldg(src + w);
    int d = __ldg(dst + w);
    int r = __ldg(et + w);
    float4 hv = ((const float4*)(h + (size_t)s * D))[lane];
    float4 rv = ((const float4*)(emb + (size_t)r * D))[lane];
    float4 v = make_float4(hv.x + rv.x, hv.y + rv.y, hv.z + rv.z, hv.w + rv.w);
    float* p = (float*)&g_S4[(size_t)d * (D / 4) + lane];
    asm volatile("red.global.add.v4.f32 [%0], {%1,%2,%3,%4};"
                 :: "l"(p), "f"(v.x), "f"(v.y), "f"(v.z), "f"(v.w) : "memory");
    if (lane == 0) g_flag[d] = 1;
}

__global__ void build_list(int N) {
    int n = blockIdx.x * blockDim.x + threadIdx.x;
    if (n < N && g_flag[n] == 0) {
        int p = atomicAdd(&g_cnt, 1);
        g_list[p] = n;
    }
}

// ---------------------------------------------------------------------------
// Weight transpose + bf16 hi/lo split:  Wt[n,k] = W[k,n]
// ---------------------------------------------------------------------------
__global__ void wtrans(const float* __restrict__ Wn,
                       const float* __restrict__ Wl,
                       const float* __restrict__ Wsk) {
    int id = blockIdx.x * 256 + threadIdx.x;          // 0..49151
    if (id >= 3 * D * D) return;
    int k = id & 127, n = (id >> 7) & 127, w = id >> 14;
    const float* W = (w == 0) ? Wn : (w == 1) ? Wl : Wsk;
    float x = W[k * D + n];
    __nv_bfloat16 hi = __float2bfloat16(x);
    float r = x - __bfloat162float(hi);
    g_WtH[w][n * D + k] = hi;
    g_WtL[w][n * D + k] = __float2bfloat16(r);
}

// ---------------------------------------------------------------------------
// Node pass: per block M=128 nodes x N=128 outputs, 512 threads = 16 warps
// tiled 4(M) x 4(N); warp tile 32x32 = 2x2 fp32 acc frags (single set).
// SMEM: A hi/lo (69632) + B hi/lo (69632) + RAW/MAIN fp32 (65536) = 204800 B.
// ---------------------------------------------------------------------------
#define OFF_AHI  0
#define OFF_ALO  34816
#define OFF_BHI  69632
#define OFF_BLO  104448
#define OFF_RAW  139264
#define SM_TOT   204800

typedef wmma::fragment<wmma::matrix_a, 16, 16, 16, __nv_bfloat16, wmma::row_major> FragA;
typedef wmma::fragment<wmma::matrix_b, 16, 16, 16, __nv_bfloat16, wmma::col_major> FragB;
typedef wmma::fragment<wmma::accumulator, 16, 16, 16, float> FragC;

// async prefetch of a 128x128 fp32 tile into RAW. Thread t copies elements
// {t, t+512, ...}; convert_A reads exactly the same set, so per-thread
// program order covers RAW reuse without extra barriers.
__device__ __forceinline__ void cpasync_raw(uint32_t sbase,
                                            const float* __restrict__ X,
                                            int node0, int N, int tid) {
    #pragma unroll 2
    for (int i = tid; i < 4096; i += 512) {
        int row = i >> 5, gr = node0 + row;
        if (gr < N)
            cp16(sbase + OFF_RAW + i * 16, X + (size_t)gr * D + (i & 31) * 4);
    }
    CP_COMMIT();
}

// RAW fp32 -> A hi/lo bf16 split tiles (optionally scaled by rowscale)
__device__ __forceinline__ void convert_A(char* sm,
                                          const float* __restrict__ rowscale,
                                          int node0, int N, int tid) {
    const float4* raw = (const float4*)(sm + OFF_RAW);
    __nv_bfloat16* sHi = (__nv_bfloat16*)(sm + OFF_AHI);
    __nv_bfloat16* sLo = (__nv_bfloat16*)(sm + OFF_ALO);
    #pragma unroll 2
    for (int i = tid; i < 4096; i += 512) {
        int row = i >> 5, c4 = i & 31, gr = node0 + row;
        float4 v = make_float4(0.f, 0.f, 0.f, 0.f);
        float sc = 1.f;
        if (gr < N) {
            v = raw[i];
            if (rowscale) sc = __ldg(rowscale + gr);
        }
        float x0 = v.x * sc, x1 = v.y * sc, x2 = v.z * sc, x3 = v.w * sc;
        __nv_bfloat16 h0 = __float2bfloat16(x0), h1 = __float2bfloat16(x1);
        __nv_bfloat16 h2 = __float2bfloat16(x2), h3 = __float2bfloat16(x3);
        __nv_bfloat162 H01; H01.x = h0; H01.y = h1;
        __nv_bfloat162 H23; H23.x = h2; H23.y = h3;
        __nv_bfloat162 L01, L23;
        L01.x = __float2bfloat16(x0 - __bfloat162float(h0));
        L01.y = __float2bfloat16(x1 - __bfloat162float(h1));
        L23.x = __float2bfloat16(x2 - __bfloat162float(h2));
        L23.y = __float2bfloat16(x3 - __bfloat162float(h3));
        int off = row * LDA + c4 * 4;
        *(__nv_bfloat162*)(sHi + off)     = H01;
        *(__nv_bfloat162*)(sHi + off + 2) = H23;
        *(__nv_bfloat162*)(sLo + off)     = L01;
        *(__nv_bfloat162*)(sLo + off + 2) = L23;
    }
}

__device__ __forceinline__ void stage_B(char* sm,
                                        const __nv_bfloat16* __restrict__ WH,
                                        const __nv_bfloat16* __restrict__ WL,
                                        int tid) {
    __nv_bfloat16* sBH = (__nv_bfloat16*)(sm + OFF_BHI);
    __nv_bfloat16* sBL = (__nv_bfloat16*)(sm + OFF_BLO);
    #pragma unroll 2
    for (int i = tid; i < 128 * 16; i += 512) {   // uint4 = 8 bf16
        int n = i >> 4, kq = i & 15;
        *(uint4*)(sBH + n * LDB + kq * 8) = *(const uint4*)(WH + n * D + kq * 8);
        *(uint4*)(sBL + n * LDB + kq * 8) = *(const uint4*)(WL + n * D + kq * 8);
    }
}

// k-outer, product-inner: 8 fragment loads per k-step feed 12 MMAs
__device__ __forceinline__ void gemm3(char* sm, FragC acc[2][2],
                                      int warp_m, int warp_n) {
    const __nv_bfloat16* sAHi = (const __nv_bfloat16*)(sm + OFF_AHI);
    const __nv_bfloat16* sALo = (const __nv_bfloat16*)(sm + OFF_ALO);
    const __nv_bfloat16* sBHi = (const __nv_bfloat16*)(sm + OFF_BHI);
    const __nv_bfloat16* sBLo = (const __nv_bfloat16*)(sm + OFF_BLO);
    #pragma unroll 1
    for (int k = 0; k < 8; k++) {
        FragA ah[2], al[2];
        FragB bh[2], bl[2];
        #pragma unroll
        for (int i = 0; i < 2; i++) {
            wmma::load_matrix_sync(ah[i],
                sAHi + (warp_m * 32 + i * 16) * LDA + k * 16, LDA);
            wmma::load_matrix_sync(al[i],
                sALo + (warp_m * 32 + i * 16) * LDA + k * 16, LDA);
        }
        #pragma unroll
        for (int j = 0; j < 2; j++) {
            wmma::load_matrix_sync(bh[j],
                sBHi + (warp_n * 32 + j * 16) * LDB + k * 16, LDB);
            wmma::load_matrix_sync(bl[j],
                sBLo + (warp_n * 32 + j * 16) * LDB + k * 16, LDB);
        }
        #pragma unroll
        for (int i = 0; i < 2; i++)
            #pragma unroll
            for (int j = 0; j < 2; j++) {
                wmma::mma_sync(acc[i][j], ah[i], bh[j], acc[i][j]);
                wmma::mma_sync(acc[i][j], ah[i], bl[j], acc[i][j]);
                wmma::mma_sync(acc[i][j], al[i], bh[j], acc[i][j]);
            }
    }
}

__global__ void __launch_bounds__(512)
node_wmma(const float* __restrict__ h, const float* __restrict__ prev,
          const float* __restrict__ norm, const float* __restrict__ bias,
          float* __restrict__ out, int N) {
    extern __shared__ char sm[];
    uint32_t sbase = smem_u32(sm);
    float* sMain = (float*)(sm + OFF_RAW);    // RAW doubles as MAIN park
    float* sGate = (float*)(sm + OFF_BHI);    // aliases B region post-gemm
    int tid = threadIdx.x;
    int wid = tid >> 5;
    int warp_m = wid & 3, warp_n = wid >> 2;
    int node0 = blockIdx.x * 128;
    FragC acc[2][2];
    #pragma unroll
    for (int i = 0; i < 2; i++)
        #pragma unroll
        for (int j = 0; j < 2; j++) wmma::fill_fragment(acc[i][j], 0.f);

    // ---- Phase 0: main += (norm.S) @ Wn ----
    cpasync_raw(sbase, (const float*)g_S4, node0, N, tid);
    CP_WAIT0();
    convert_A(sm, norm, node0, N, tid);
    stage_B(sm, g_WtH[0], g_WtL[0], tid);
    __syncthreads();
    cpasync_raw(sbase, h, node0, N, tid);     // prefetch h behind gemm
    gemm3(sm, acc, warp_m, warp_n);
    CP_WAIT0();
    __syncthreads();                          // gemm done reading A/B

    // ---- Phase 1: main += h @ Wl ----
    convert_A(sm, nullptr, node0, N, tid);
    stage_B(sm, g_WtH[1], g_WtL[1], tid);
    __syncthreads();
    cpasync_raw(sbase, prev, node0, N, tid);  // prefetch prev behind gemm
    gemm3(sm, acc, warp_m, warp_n);
    CP_WAIT0();
    __syncthreads();                          // gemm done reading A/B

    // ---- Phase 2: convert prev, park main into RAW, gate = prev @ Wsk ----
    convert_A(sm, nullptr, node0, N, tid);
    stage_B(sm, g_WtH[2], g_WtL[2], tid);
    __syncthreads();                          // all RAW reads (convert) done
    #pragma unroll
    for (int i = 0; i < 2; i++)               // park main (acc still holds it)
        #pragma unroll
        for (int j = 0; j < 2; j++)
            wmma::store_matrix_sync(
                sMain + (warp_m * 32 + i * 16) * 128 + warp_n * 32 + j * 16,
                acc[i][j], 128, wmma::mem_row_major);
    #pragma unroll
    for (int i = 0; i < 2; i++)
        #pragma unroll
        for (int j = 0; j < 2; j++) wmma::fill_fragment(acc[i][j], 0.f);
    gemm3(sm, acc, warp_m, warp_n);
    __syncthreads();                          // B reads done; alias as sGate
    #pragma unroll
    for (int i = 0; i < 2; i++)
        #pragma unroll
        for (int j = 0; j < 2; j++)
            wmma::store_matrix_sync(
                sGate + (warp_m * 32 + i * 16) * 128 + warp_n * 32 + j * 16,
                acc[i][j], 128, wmma::mem_row_major);
    __syncthreads();

    // ---- Epilogue: out = relu(g*main + (1-g)*prev); prev from A tiles ----
    const __nv_bfloat16* sHi = (const __nv_bfloat16*)(sm + OFF_AHI);
    const __nv_bfloat16* sLo = (const __nv_bfloat16*)(sm + OFF_ALO);
    #pragma unroll 2
    for (int i = tid; i < 4096; i += 512) {
        int m = i >> 5, c4 = i & 31;
        if (node0 + m >= N) continue;
        float4 mn = ((const float4*)sMain)[m * 32 + c4];
        float4 z  = ((const float4*)sGate)[m * 32 + c4];
        float4 bz = ((const float4*)bias)[c4];
        int off = m * LDA + c4 * 4;
        __nv_bfloat162 H01 = *(const __nv_bfloat162*)(sHi + off);
        __nv_bfloat162 H23 = *(const __nv_bfloat162*)(sHi + off + 2);
        __nv_bfloat162 L01 = *(const __nv_bfloat162*)(sLo + off);
        __nv_bfloat162 L23 = *(const __nv_bfloat162*)(sLo + off + 2);
        float p0 = __bfloat162float(H01.x) + __bfloat162float(L01.x);
        float p1 = __bfloat162float(H01.y) + __bfloat162float(L01.y);
        float p2 = __bfloat162float(H23.x) + __bfloat162float(L23.x);
        float p3 = __bfloat162float(H23.y) + __bfloat162float(L23.y);
        float4 o;
        float g;
        g = 1.f / (1.f + __expf(-(z.x + bz.x)));
        o.x = fmaxf(g * mn.x + (1.f - g) * p0, 0.f);
        g = 1.f / (1.f + __expf(-(z.y + bz.y)));
        o.y = fmaxf(g * mn.y + (1.f - g) * p1, 0.f);
        g = 1.f / (1.f + __expf(-(z.z + bz.z)));
        o.z = fmaxf(g * mn.z + (1.f - g) * p2, 0.f);
        g = 1.f / (1.f + __expf(-(z.w + bz.w)));
        o.w = fmaxf(g * mn.w + (1.f - g) * p3, 0.f);
        ((float4*)(out + (size_t)(node0 + m) * D))[c4] = o;
    }
}

// ---------------------------------------------------------------------------
// Fix-up for degree-0 nodes (agg==0): out = relu(g*(h@We) + (1-g)*prev)
// ---------------------------------------------------------------------------
__global__ void fix_kernel(const float* __restrict__ h,
                           const float* __restrict__ prev,
                           const float* __restrict__ We,
                           const float* __restrict__ Wsk,
                           const float* __restrict__ bias,
                           float* __restrict__ out) {
    __shared__ float sh[D], sp[D];
    int t = threadIdx.x;
    int cnt = g_cnt;
    for (int ii = blockIdx.x; ii < cnt; ii += gridDim.x) {
        int node = g_list[ii];
        __syncthreads();
        sh[t] = h[(size_t)node * D + t];
        sp[t] = prev[(size_t)node * D + t];
        __syncthreads();
        float lp = 0.f, sk = 0.f;
        #pragma unroll 8
        for (int k = 0; k < D; k++) {
            lp = fmaf(sh[k], __ldg(We  + k * D + t), lp);
            sk = fmaf(sp[k], __ldg(Wsk + k * D + t), sk);
        }
        float g = 1.f / (1.f + __expf(-(sk + bias[t])));
        out[(size_t)node * D + t] = fmaxf(g * lp + (1.f - g) * sp[t], 0.f);
    }
}

// ---------------------------------------------------------------------------
extern "C" void kernel_launch(void* const* d_in, const int* in_sizes, int n_in,
                              void* d_out, int out_size) {
    const float* h    = (const float*)d_in[0];
    const float* prev = (const float*)d_in[1];
    const float* emb  = (const float*)d_in[2];
    const float* norm = (const float*)d_in[3];
    const float* Wn   = (const float*)d_in[4];
    const float* Wl   = (const float*)d_in[5];
    const float* We   = (const float*)d_in[6];
    const float* Wsk  = (const float*)d_in[7];
    const float* bias = (const float*)d_in[8];
    const int* src = (const int*)d_in[9];     // int32 (JAX x64-disabled)
    const int* dst = (const int*)d_in[10];
    const int* et  = (const int*)d_in[11];
    int N = in_sizes[3];
    if (N > NMAX) N = NMAX;
    int E = in_sizes[9];
    float* out = (float*)d_out;

    void *pS, *pF, *pC;
    cudaGetSymbolAddress(&pS, g_S4);
    cudaGetSymbolAddress(&pF, g_flag);
    cudaGetSymbolAddress(&pC, g_cnt);
    cudaMemsetAsync(pS, 0, (size_t)N * D * sizeof(float), 0);
    cudaMemsetAsync(pF, 0, (size_t)N * sizeof(int), 0);
    cudaMemsetAsync(pC, 0, sizeof(int), 0);

    wtrans<<<192, 256>>>(Wn, Wl, Wsk);

    int edgeBlocks = (E + 7) / 8;
    edge_kernel<<<edgeBlocks, 256>>>(h, emb, src, dst, et, E);

    build_list<<<(N + 255) / 256, 256>>>(N);

    cudaFuncSetAttribute(node_wmma,
                         cudaFuncAttributeMaxDynamicSharedMemorySize, SM_TOT);
    node_wmma<<<(N + 127) / 128, 512, SM_TOT>>>(h, prev, norm, bias, out, N);

    fix_kernel<<<2048, 128>>>(h, prev, We, Wsk, bias, out);
}

// round 17
// speedup vs baseline: 1.8474x; 1.1824x over previous
#include <cuda_runtime.h>
#include <cuda_bf16.h>
#include <mma.h>
#include <math.h>
#include <stdint.h>

using namespace nvcuda;

// ---------------------------------------------------------------------------
// RGCN layer (plain sm_103 target: WMMA bf16 + cp.async, no tcgen05).
//   CSR bucket build (cap 96, no scan) -> warp-per-dst gather aggregation:
//     S[d] = norm[d] * sum_{e: dst=d} (h[src] + emb_rel[etype])
//   main  = S @ Wn + h @ Wl            (phases 0-1, ONE acc set, K-concat)
//   gate  = prev @ Wsk                 (phase 2, same acc refilled)
//   out   = relu(g*main + (1-g)*prev),  g = sigmoid(gate + b)
//   deg-0 nodes (~250): recompute loop term with W_evolve in fix_kernel.
// Gather-side aggregation replaces the scatter red.add pass: L2 traffic
// drops from ~920MB (512B gather + 512B atomic RMW per edge + 51MB memset)
// to ~370MB (gather + single coalesced S write, no memset).
// Split precision GEMM: x = hi+lo bf16; hi*hi+hi*lo+lo*hi, fp32 acc.
// ---------------------------------------------------------------------------

#define D       128
#define NMAX    100000
#define LDA     136
#define LDB     136
#define CAP     96
#define OVF_MAX 2000000

__device__ float4   g_S4[NMAX * (D / 4)];   // 51.2 MB aggregated messages
__device__ uint32_t g_csr[(size_t)NMAX * CAP];  // 38.4 MB bucket CSR
__device__ int      g_deg[NMAX];            // in-degree / bucket cursor
__device__ uint64_t g_ovf[OVF_MAX];         // overflow edges (normally empty)
__device__ int      g_ovf_cnt;
__device__ int      g_list[NMAX];
__device__ int      g_cnt;
__device__ __nv_bfloat16 g_WtH[3][D * D];   // W^T hi (Wn, Wl, Wsk), [n*D+k]
__device__ __nv_bfloat16 g_WtL[3][D * D];   // W^T lo

// ---------------------------------------------------------------------------
__device__ __forceinline__ uint32_t smem_u32(const void* p) {
    uint32_t a;
    asm("{ .reg .u64 t; cvta.to.shared.u64 t, %1; cvt.u32.u64 %0, t; }"
        : "=r"(a) : "l"(p));
    return a;
}
__device__ __forceinline__ void cp16(uint32_t saddr, const void* g) {
    asm volatile("cp.async.cg.shared.global [%0], [%1], 16;"
                 :: "r"(saddr), "l"(g));
}
#define CP_COMMIT() asm volatile("cp.async.commit_group;" ::: "memory")
#define CP_WAIT0()  asm volatile("cp.async.wait_group 0;" ::: "memory")

// ---------------------------------------------------------------------------
// CSR bucket fill: 1 thread/edge. Packed entry = src | (etype<<20).
// ---------------------------------------------------------------------------
__global__ void fill_kernel(const int* __restrict__ src,
                            const int* __restrict__ dst,
                            const int* __restrict__ et, int E) {
    int e = blockIdx.x * 256 + threadIdx.x;
    if (e >= E) return;
    int d = __ldg(dst + e);
    uint32_t ent = (uint32_t)__ldg(src + e) | ((uint32_t)__ldg(et + e) << 20);
    int slot = atomicAdd(&g_deg[d], 1);
    if (slot < CAP) {
        g_csr[(size_t)d * CAP + slot] = ent;
    } else {
        int o = atomicAdd(&g_ovf_cnt, 1);
        if (o < OVF_MAX) g_ovf[o] = (uint64_t)ent | ((uint64_t)d << 32);
    }
}

// ---------------------------------------------------------------------------
// Gather aggregation: one warp per dst; lane l owns floats [4l,4l+4).
// Writes S[d] = norm[d] * sum(h[src]+emb[et]) exactly once (zeros for deg 0).
// ---------------------------------------------------------------------------
__global__ void agg_kernel(const float* __restrict__ h,
                           const float* __restrict__ emb,
                           const float* __restrict__ norm, int N) {
    int d = blockIdx.x * 8 + (threadIdx.x >> 5);
    if (d >= N) return;
    int lane = threadIdx.x & 31;
    int c = g_deg[d];
    if (c > CAP) c = CAP;
    const uint32_t* row = &g_csr[(size_t)d * CAP];
    uint32_t myent = (lane < c) ? row[lane] : 0;   // covers c <= 32 in one load
    float4 a0 = make_float4(0.f, 0.f, 0.f, 0.f);
    float4 a1 = make_float4(0.f, 0.f, 0.f, 0.f);
    for (int i = 0; i < c; i += 2) {
        uint32_t e0 = (i < 32) ? __shfl_sync(0xFFFFFFFFu, myent, i) : row[i];
        int s0 = e0 & 0xFFFFF, r0 = e0 >> 20;
        float4 hv = ((const float4*)(h + (size_t)s0 * D))[lane];
        float4 rv = ((const float4*)(emb + (size_t)r0 * D))[lane];
        a0.x += hv.x + rv.x; a0.y += hv.y + rv.y;
        a0.z += hv.z + rv.z; a0.w += hv.w + rv.w;
        if (i + 1 < c) {
            uint32_t e1 = (i + 1 < 32) ? __shfl_sync(0xFFFFFFFFu, myent, i + 1)
                                       : row[i + 1];
            int s1 = e1 & 0xFFFFF, r1 = e1 >> 20;
            float4 hv1 = ((const float4*)(h + (size_t)s1 * D))[lane];
            float4 rv1 = ((const float4*)(emb + (size_t)r1 * D))[lane];
            a1.x += hv1.x + rv1.x; a1.y += hv1.y + rv1.y;
            a1.z += hv1.z + rv1.z; a1.w += hv1.w + rv1.w;
        }
    }
    float nv = __ldg(norm + d);
    float4 a = make_float4((a0.x + a1.x) * nv, (a0.y + a1.y) * nv,
                           (a0.z + a1.z) * nv, (a0.w + a1.w) * nv);
    g_S4[(size_t)d * 32 + lane] = a;
}

// Overflow fallback (normally 0 entries): red.add onto already-written S.
__global__ void ovf_kernel(const float* __restrict__ h,
                           const float* __restrict__ emb,
                           const float* __restrict__ norm) {
    int n = g_ovf_cnt;
    if (n > OVF_MAX) n = OVF_MAX;
    int w = (blockIdx.x * blockDim.x + threadIdx.x) >> 5;
    int nw = (gridDim.x * blockDim.x) >> 5;
    int lane = threadIdx.x & 31;
    for (; w < n; w += nw) {
        uint64_t p = g_ovf[w];
        uint32_t ent = (uint32_t)p;
        int d = (int)(p >> 32);
        int s = ent & 0xFFFFF, r = ent >> 20;
        float nv = __ldg(norm + d);
        float4 hv = ((const float4*)(h + (size_t)s * D))[lane];
        float4 rv = ((const float4*)(emb + (size_t)r * D))[lane];
        float4 v = make_float4((hv.x + rv.x) * nv, (hv.y + rv.y) * nv,
                               (hv.z + rv.z) * nv, (hv.w + rv.w) * nv);
        float* pp = (float*)&g_S4[(size_t)d * 32 + lane];
        asm volatile("red.global.add.v4.f32 [%0], {%1,%2,%3,%4};"
                     :: "l"(pp), "f"(v.x), "f"(v.y), "f"(v.z), "f"(v.w)
                     : "memory");
    }
}

__global__ void build_list(int N) {
    int n = blockIdx.x * blockDim.x + threadIdx.x;
    if (n < N && g_deg[n] == 0) {
        int p = atomicAdd(&g_cnt, 1);
        g_list[p] = n;
    }
}

// ---------------------------------------------------------------------------
// Weight transpose + bf16 hi/lo split:  Wt[n,k] = W[k,n]
// ---------------------------------------------------------------------------
__global__ void wtrans(const float* __restrict__ Wn,
                       const float* __restrict__ Wl,
                       const float* __restrict__ Wsk) {
    int id = blockIdx.x * 256 + threadIdx.x;          // 0..49151
    if (id >= 3 * D * D) return;
    int k = id & 127, n = (id >> 7) & 127, w = id >> 14;
    const float* W = (w == 0) ? Wn : (w == 1) ? Wl : Wsk;
    float x = W[k * D + n];
    __nv_bfloat16 hi = __float2bfloat16(x);
    float r = x - __bfloat162float(hi);
    g_WtH[w][n * D + k] = hi;
    g_WtL[w][n * D + k] = __float2bfloat16(r);
}

// ---------------------------------------------------------------------------
// Node pass: per block M=128 nodes x N=128 outputs, 512 threads = 16 warps
// tiled 4(M) x 4(N); warp tile 32x32 = 2x2 fp32 acc frags (single set).
// SMEM: A hi/lo (69632) + B hi/lo (69632) + RAW/MAIN fp32 (65536) = 204800 B.
// ---------------------------------------------------------------------------
#define OFF_AHI  0
#define OFF_ALO  34816
#define OFF_BHI  69632
#define OFF_BLO  104448
#define OFF_RAW  139264
#define SM_TOT   204800

typedef wmma::fragment<wmma::matrix_a, 16, 16, 16, __nv_bfloat16, wmma::row_major> FragA;
typedef wmma::fragment<wmma::matrix_b, 16, 16, 16, __nv_bfloat16, wmma::col_major> FragB;
typedef wmma::fragment<wmma::accumulator, 16, 16, 16, float> FragC;

__device__ __forceinline__ void cpasync_raw(uint32_t sbase,
                                            const float* __restrict__ X,
                                            int node0, int N, int tid) {
    #pragma unroll 2
    for (int i = tid; i < 4096; i += 512) {
        int row = i >> 5, gr = node0 + row;
        if (gr < N)
            cp16(sbase + OFF_RAW + i * 16, X + (size_t)gr * D + (i & 31) * 4);
    }
    CP_COMMIT();
}

__device__ __forceinline__ void convert_A(char* sm,
                                          int node0, int N, int tid) {
    const float4* raw = (const float4*)(sm + OFF_RAW);
    __nv_bfloat16* sHi = (__nv_bfloat16*)(sm + OFF_AHI);
    __nv_bfloat16* sLo = (__nv_bfloat16*)(sm + OFF_ALO);
    #pragma unroll 2
    for (int i = tid; i < 4096; i += 512) {
        int row = i >> 5, c4 = i & 31, gr = node0 + row;
        float4 v = make_float4(0.f, 0.f, 0.f, 0.f);
        if (gr < N) v = raw[i];
        float x0 = v.x, x1 = v.y, x2 = v.z, x3 = v.w;
        __nv_bfloat16 h0 = __float2bfloat16(x0), h1 = __float2bfloat16(x1);
        __nv_bfloat16 h2 = __float2bfloat16(x2), h3 = __float2bfloat16(x3);
        __nv_bfloat162 H01; H01.x = h0; H01.y = h1;
        __nv_bfloat162 H23; H23.x = h2; H23.y = h3;
        __nv_bfloat162 L01, L23;
        L01.x = __float2bfloat16(x0 - __bfloat162float(h0));
        L01.y = __float2bfloat16(x1 - __bfloat162float(h1));
        L23.x = __float2bfloat16(x2 - __bfloat162float(h2));
        L23.y = __float2bfloat16(x3 - __bfloat162float(h3));
        int off = row * LDA + c4 * 4;
        *(__nv_bfloat162*)(sHi + off)     = H01;
        *(__nv_bfloat162*)(sHi + off + 2) = H23;
        *(__nv_bfloat162*)(sLo + off)     = L01;
        *(__nv_bfloat162*)(sLo + off + 2) = L23;
    }
}

__device__ __forceinline__ void stage_B(char* sm,
                                        const __nv_bfloat16* __restrict__ WH,
                                        const __nv_bfloat16* __restrict__ WL,
                                        int tid) {
    __nv_bfloat16* sBH = (__nv_bfloat16*)(sm + OFF_BHI);
    __nv_bfloat16* sBL = (__nv_bfloat16*)(sm + OFF_BLO);
    #pragma unroll 2
    for (int i = tid; i < 128 * 16; i += 512) {   // uint4 = 8 bf16
        int n = i >> 4, kq = i & 15;
        *(uint4*)(sBH + n * LDB + kq * 8) = *(const uint4*)(WH + n * D + kq * 8);
        *(uint4*)(sBL + n * LDB + kq * 8) = *(const uint4*)(WL + n * D + kq * 8);
    }
}

// k-outer, product-inner: 8 fragment loads per k-step feed 12 MMAs
__device__ __forceinline__ void gemm3(char* sm, FragC acc[2][2],
                                      int warp_m, int warp_n) {
    const __nv_bfloat16* sAHi = (const __nv_bfloat16*)(sm + OFF_AHI);
    const __nv_bfloat16* sALo = (const __nv_bfloat16*)(sm + OFF_ALO);
    const __nv_bfloat16* sBHi = (const __nv_bfloat16*)(sm + OFF_BHI);
    const __nv_bfloat16* sBLo = (const __nv_bfloat16*)(sm + OFF_BLO);
    #pragma unroll 1
    for (int k = 0; k < 8; k++) {
        FragA ah[2], al[2];
        FragB bh[2], bl[2];
        #pragma unroll
        for (int i = 0; i < 2; i++) {
            wmma::load_matrix_sync(ah[i],
                sAHi + (warp_m * 32 + i * 16) * LDA + k * 16, LDA);
            wmma::load_matrix_sync(al[i],
                sALo + (warp_m * 32 + i * 16) * LDA + k * 16, LDA);
        }
        #pragma unroll
        for (int j = 0; j < 2; j++) {
            wmma::load_matrix_sync(bh[j],
                sBHi + (warp_n * 32 + j * 16) * LDB + k * 16, LDB);
            wmma::load_matrix_sync(bl[j],
                sBLo + (warp_n * 32 + j * 16) * LDB + k * 16, LDB);
        }
        #pragma unroll
        for (int i = 0; i < 2; i++)
            #pragma unroll
            for (int j = 0; j < 2; j++) {
                wmma::mma_sync(acc[i][j], ah[i], bh[j], acc[i][j]);
                wmma::mma_sync(acc[i][j], ah[i], bl[j], acc[i][j]);
                wmma::mma_sync(acc[i][j], al[i], bh[j], acc[i][j]);
            }
    }
}

__global__ void __launch_bounds__(512)
node_wmma(const float* __restrict__ h, const float* __restrict__ prev,
          const float* __restrict__ bias,
          float* __restrict__ out, int N) {
    extern __shared__ char sm[];
    uint32_t sbase = smem_u32(sm);
    float* sMain = (float*)(sm + OFF_RAW);    // RAW doubles as MAIN park
    float* sGate = (float*)(sm + OFF_BHI);    // aliases B region post-gemm
    int tid = threadIdx.x;
    int wid = tid >> 5;
    int warp_m = wid & 3, warp_n = wid >> 2;
    int node0 = blockIdx.x * 128;
    FragC acc[2][2];
    #pragma unroll
    for (int i = 0; i < 2; i++)
        #pragma unroll
        for (int j = 0; j < 2; j++) wmma::fill_fragment(acc[i][j], 0.f);

    // ---- Phase 0: main += S @ Wn  (norm pre-folded into S by agg) ----
    cpasync_raw(sbase, (const float*)g_S4, node0, N, tid);
    CP_WAIT0();
    convert_A(sm, node0, N, tid);
    stage_B(sm, g_WtH[0], g_WtL[0], tid);
    __syncthreads();
    cpasync_raw(sbase, h, node0, N, tid);     // prefetch h behind gemm
    gemm3(sm, acc, warp_m, warp_n);
    CP_WAIT0();
    __syncthreads();                          // gemm done reading A/B

    // ---- Phase 1: main += h @ Wl ----
    convert_A(sm, node0, N, tid);
    stage_B(sm, g_WtH[1], g_WtL[1], tid);
    __syncthreads();
    cpasync_raw(sbase, prev, node0, N, tid);  // prefetch prev behind gemm
    gemm3(sm, acc, warp_m, warp_n);
    CP_WAIT0();
    __syncthreads();                          // gemm done reading A/B

    // ---- Phase 2: convert prev, park main into RAW, gate = prev @ Wsk ----
    convert_A(sm, node0, N, tid);
    stage_B(sm, g_WtH[2], g_WtL[2], tid);
    __syncthreads();                          // all RAW reads (convert) done
    #pragma unroll
    for (int i = 0; i < 2; i++)               // park main (acc still holds it)
        #pragma unroll
        for (int j = 0; j < 2; j++)
            wmma::store_matrix_sync(
                sMain + (warp_m * 32 + i * 16) * 128 + warp_n * 32 + j * 16,
                acc[i][j], 128, wmma::mem_row_major);
    #pragma unroll
    for (int i = 0; i < 2; i++)
        #pragma unroll
        for (int j = 0; j < 2; j++) wmma::fill_fragment(acc[i][j], 0.f);
    gemm3(sm, acc, warp_m, warp_n);
    __syncthreads();                          // B reads done; alias as sGate
    #pragma unroll
    for (int i = 0; i < 2; i++)
        #pragma unroll
        for (int j = 0; j < 2; j++)
            wmma::store_matrix_sync(
                sGate + (warp_m * 32 + i * 16) * 128 + warp_n * 32 + j * 16,
                acc[i][j], 128, wmma::mem_row_major);
    __syncthreads();

    // ---- Epilogue: out = relu(g*main + (1-g)*prev); prev from A tiles ----
    const __nv_bfloat16* sHi = (const __nv_bfloat16*)(sm + OFF_AHI);
    const __nv_bfloat16* sLo = (const __nv_bfloat16*)(sm + OFF_ALO);
    #pragma unroll 2
    for (int i = tid; i < 4096; i += 512) {
        int m = i >> 5, c4 = i & 31;
        if (node0 + m >= N) continue;
        float4 mn = ((const float4*)sMain)[m * 32 + c4];
        float4 z  = ((const float4*)sGate)[m * 32 + c4];
        float4 bz = ((const float4*)bias)[c4];
        int off = m * LDA + c4 * 4;
        __nv_bfloat162 H01 = *(const __nv_bfloat162*)(sHi + off);
        __nv_bfloat162 H23 = *(const __nv_bfloat162*)(sHi + off + 2);
        __nv_bfloat162 L01 = *(const __nv_bfloat162*)(sLo + off);
        __nv_bfloat162 L23 = *(const __nv_bfloat162*)(sLo + off + 2);
        float p0 = __bfloat162float(H01.x) + __bfloat162float(L01.x);
        float p1 = __bfloat162float(H01.y) + __bfloat162float(L01.y);
        float p2 = __bfloat162float(H23.x) + __bfloat162float(L23.x);
        float p3 = __bfloat162float(H23.y) + __bfloat162float(L23.y);
        float4 o;
        float g;
        g = 1.f / (1.f + __expf(-(z.x + bz.x)));
        o.x = fmaxf(g * mn.x + (1.f - g) * p0, 0.f);
        g = 1.f / (1.f + __expf(-(z.y + bz.y)));
        o.y = fmaxf(g * mn.y + (1.f - g) * p1, 0.f);
        g = 1.f / (1.f + __expf(-(z.z + bz.z)));
        o.z = fmaxf(g * mn.z + (1.f - g) * p2, 0.f);
        g = 1.f / (1.f + __expf(-(z.w + bz.w)));
        o.w = fmaxf(g * mn.w + (1.f - g) * p3, 0.f);
        ((float4*)(out + (size_t)(node0 + m) * D))[c4] = o;
    }
}

// ---------------------------------------------------------------------------
// Fix-up for degree-0 nodes (agg==0): out = relu(g*(h@We) + (1-g)*prev)
// ---------------------------------------------------------------------------
__global__ void fix_kernel(const float* __restrict__ h,
                           const float* __restrict__ prev,
                           const float* __restrict__ We,
                           const float* __restrict__ Wsk,
                           const float* __restrict__ bias,
                           float* __restrict__ out) {
    __shared__ float sh[D], sp[D];
    int t = threadIdx.x;
    int cnt = g_cnt;
    for (int ii = blockIdx.x; ii < cnt; ii += gridDim.x) {
        int node = g_list[ii];
        __syncthreads();
        sh[t] = h[(size_t)node * D + t];
        sp[t] = prev[(size_t)node * D + t];
        __syncthreads();
        float lp = 0.f, sk = 0.f;
        #pragma unroll 8
        for (int k = 0; k < D; k++) {
            lp = fmaf(sh[k], __ldg(We  + k * D + t), lp);
            sk = fmaf(sp[k], __ldg(Wsk + k * D + t), sk);
        }
        float g = 1.f / (1.f + __expf(-(sk + bias[t])));
        out[(size_t)node * D + t] = fmaxf(g * lp + (1.f - g) * sp[t], 0.f);
    }
}

// ---------------------------------------------------------------------------
extern "C" void kernel_launch(void* const* d_in, const int* in_sizes, int n_in,
                              void* d_out, int out_size) {
    const float* h    = (const float*)d_in[0];
    const float* prev = (const float*)d_in[1];
    const float* emb  = (const float*)d_in[2];
    const float* norm = (const float*)d_in[3];
    const float* Wn   = (const float*)d_in[4];
    const float* Wl   = (const float*)d_in[5];
    const float* We   = (const float*)d_in[6];
    const float* Wsk  = (const float*)d_in[7];
    const float* bias = (const float*)d_in[8];
    const int* src = (const int*)d_in[9];     // int32 (JAX x64-disabled)
    const int* dst = (const int*)d_in[10];
    const int* et  = (const int*)d_in[11];
    int N = in_sizes[3];
    if (N > NMAX) N = NMAX;
    int E = in_sizes[9];
    float* out = (float*)d_out;

    void *pD, *pO, *pC;
    cudaGetSymbolAddress(&pD, g_deg);
    cudaGetSymbolAddress(&pO, g_ovf_cnt);
    cudaGetSymbolAddress(&pC, g_cnt);
    cudaMemsetAsync(pD, 0, (size_t)N * sizeof(int), 0);
    cudaMemsetAsync(pO, 0, sizeof(int), 0);
    cudaMemsetAsync(pC, 0, sizeof(int), 0);

    wtrans<<<192, 256>>>(Wn, Wl, Wsk);

    fill_kernel<<<(E + 255) / 256, 256>>>(src, dst, et, E);
    build_list<<<(N + 255) / 256, 256>>>(N);
    agg_kernel<<<(N + 7) / 8, 256>>>(h, emb, norm, N);
    ovf_kernel<<<32, 256>>>(h, emb, norm);

    cudaFuncSetAttribute(node_wmma,
                         cudaFuncAttributeMaxDynamicSharedMemorySize, SM_TOT);
    node_wmma<<<(N + 127) / 128, 512, SM_TOT>>>(h, prev, bias, out, N);

    fix_kernel<<<2048, 128>>>(h, prev, We, Wsk, bias, out);
}